// round 2
// baseline (speedup 1.0000x reference)
#include <cuda_runtime.h>

#define N_   16
#define C_   512
#define H_   64
#define W_   64
#define GRP  4
#define CG   128
#define MIP  16
#define EPS_ 1e-5f

// Scratch (allocation-free). Counters/flags are MONOTONIC across graph
// replays: each launch adds exactly 128 to each group's counter and 1 to its
// flag, so generation = old/128 identifies this launch with no reset needed.
__device__ float g_gh[N_ * C_ * H_];   // [n][ch][h]  mean over w
__device__ float g_gw[N_ * C_ * W_];   // [n][ch][w]  mean over h
__device__ float g_ah[N_ * C_ * H_];   // sigmoid gate along h
__device__ float g_aw[N_ * C_ * W_];   // sigmoid gate along w
__device__ int   g_cnt[N_ * GRP];      // pooled-CTA arrival counter per group
__device__ int   g_flag[N_ * GRP];     // gates-ready generation per group

__global__ __launch_bounds__(256) void fused_kernel(
    const float* __restrict__ x,
    const float* __restrict__ W1, const float* __restrict__ b1,
    const float* __restrict__ gamma, const float* __restrict__ beta,
    const float* __restrict__ mean_, const float* __restrict__ var_,
    const float* __restrict__ Wh, const float* __restrict__ bh,
    const float* __restrict__ Ww, const float* __restrict__ bw,
    float* __restrict__ out)
{
    __shared__ float xs[64 * 65];      // padded tile: conflict-free rows+cols
    __shared__ float W1s[MIP * CG];    // MLP weights (only used by 1 CTA/group)
    __shared__ float ys[MIP * 128];    // post-activation y (MLP CTA only)
    __shared__ float sa[64], swv[64];  // gates for this channel
    __shared__ int   s_old;

    const int img = blockIdx.x;                 // n*512 + ch
    const int n  = img >> 9;
    const int ch = img & 511;
    const int g  = ch >> 7;                     // group within channel dim
    const int grpid = n * GRP + g;
    const int tid = threadIdx.x;

    // ---- phase A: load tile, pool rows & cols ----
    const float4* __restrict__ xp = (const float4*)(x + (size_t)img * 4096);
#pragma unroll
    for (int k = 0; k < 4; k++) {
        int idx4 = k * 256 + tid;
        float4 v = xp[idx4];
        int f = idx4 << 2;
        int h = f >> 6, w = f & 63;
        float* p = &xs[h * 65 + w];
        p[0] = v.x; p[1] = v.y; p[2] = v.z; p[3] = v.w;
    }
    __syncthreads();

    if (tid < 64) {
        float s = 0.f;
#pragma unroll
        for (int i = 0; i < 64; i++) s += xs[tid * 65 + i];
        g_gh[img * 64 + tid] = s * (1.f / 64.f);
    } else if (tid < 128) {
        int w = tid - 64;
        float s = 0.f;
#pragma unroll
        for (int i = 0; i < 64; i++) s += xs[i * 65 + w];
        g_gw[img * 64 + w] = s * (1.f / 64.f);
    }
    __threadfence();                 // release our gh/gw writes (gpu scope)
    __syncthreads();

    if (tid == 0) s_old = atomicAdd(&g_cnt[grpid], 1);
    __syncthreads();
    const int old = s_old;
    const int gen = old >> 7;        // launch generation for this group

    if ((old & 127) == 127) {
        // ---- phase B (one CTA per group): MLP + BN + hswish + gate GEMMs ----
        __threadfence();             // acquire all 128 CTAs' pooled writes

        for (int i = tid; i < MIP * CG; i += 256) W1s[i] = W1[i];
        __syncthreads();

        if (tid < 128) {
            const int l = tid;
            const float* __restrict__ src = (l < 64)
                ? &g_gh[((size_t)n * C_ + g * CG) * 64 + l]
                : &g_gw[((size_t)n * C_ + g * CG) * 64 + (l - 64)];

            float acc[MIP];
#pragma unroll
            for (int m = 0; m < MIP; m++) acc[m] = 0.f;
#pragma unroll 4
            for (int c2 = 0; c2 < CG; c2++) {
                float yc = src[c2 * 64];
#pragma unroll
                for (int m = 0; m < MIP; m++) acc[m] += W1s[m * CG + c2] * yc;
            }
#pragma unroll
            for (int m = 0; m < MIP; m++) {
                float sc = gamma[m] * rsqrtf(var_[m] + EPS_);     // uniform LDG
                float v = (acc[m] + b1[m]) * sc + (beta[m] - mean_[m] * sc);
                float r = fminf(fmaxf(v + 3.f, 0.f), 6.f);
                ys[m * 128 + l] = v * r * (1.f / 6.f);
            }
        }
        __syncthreads();

        if (tid < 128) {
            const int cc = tid;
            float whr[MIP], wwr[MIP];
#pragma unroll
            for (int m = 0; m < MIP; m++) {
                whr[m] = Wh[cc * MIP + m];
                wwr[m] = Ww[cc * MIP + m];
            }
            const float bhc = bh[cc], bwc = bw[cc];
            const size_t base = ((size_t)n * C_ + g * CG + cc) * 64;
#pragma unroll 2
            for (int l2 = 0; l2 < 64; l2++) {
                float sh = bhc, sw2 = bwc;
#pragma unroll
                for (int m = 0; m < MIP; m++) {
                    sh  += whr[m] * ys[m * 128 + l2];
                    sw2 += wwr[m] * ys[m * 128 + l2 + 64];
                }
                g_ah[base + l2] = 1.f / (1.f + __expf(-sh));
                g_aw[base + l2] = 1.f / (1.f + __expf(-sw2));
            }
        }
        __threadfence();             // release gate writes
        __syncthreads();
        if (tid == 0) atomicAdd(&g_flag[grpid], 1);
    } else {
        // ---- spin until this launch's gates are published ----
        if (tid == 0) {
            const int* fp = &g_flag[grpid];
            while (true) {
                int f;
                asm volatile("ld.acquire.gpu.global.s32 %0, [%1];"
                             : "=r"(f) : "l"(fp));
                if (f > gen) break;
                __nanosleep(128);
            }
        }
        __syncthreads();
    }

    // ---- phase C: apply gates to the smem-resident tile, shuffled write ----
    if (tid < 64)       sa[tid]       = g_ah[img * 64 + tid];
    else if (tid < 128) swv[tid - 64] = g_aw[img * 64 + (tid - 64)];
    __syncthreads();

    const int fc = (ch & 3) * 128 + (ch >> 2);     // channel shuffle
    float4* __restrict__ op = (float4*)(out + ((size_t)n * 512 + fc) * 4096);
#pragma unroll
    for (int k = 0; k < 4; k++) {
        int idx4 = k * 256 + tid;
        int f = idx4 << 2;
        int h = f >> 6, w = f & 63;
        const float a = sa[h];
        const float* p = &xs[h * 65 + w];
        float4 v;
        v.x = p[0] * a * swv[w];
        v.y = p[1] * a * swv[w + 1];
        v.z = p[2] * a * swv[w + 2];
        v.w = p[3] * a * swv[w + 3];
        op[idx4] = v;
    }
}

extern "C" void kernel_launch(void* const* d_in, const int* in_sizes, int n_in,
                              void* d_out, int out_size) {
    const float* x     = (const float*)d_in[0];
    const float* W1    = (const float*)d_in[1];
    const float* b1    = (const float*)d_in[2];
    const float* gamma = (const float*)d_in[3];
    const float* beta  = (const float*)d_in[4];
    const float* mean_ = (const float*)d_in[5];
    const float* var_  = (const float*)d_in[6];
    const float* Wh    = (const float*)d_in[7];
    const float* bh    = (const float*)d_in[8];
    const float* Ww    = (const float*)d_in[9];
    const float* bw    = (const float*)d_in[10];
    float* out = (float*)d_out;

    fused_kernel<<<N_ * C_, 256>>>(x, W1, b1, gamma, beta, mean_, var_,
                                   Wh, bh, Ww, bw, out);
}

// round 3
// speedup vs baseline: 5.8675x; 5.8675x over previous
#include <cuda_runtime.h>

#define N_   16
#define C_   512
#define H_   64
#define W_   64
#define GRP  4
#define CG   128
#define MIP  16
#define EPS_ 1e-5f

// Scratch (allocation-free): pooled rows/cols and gate vectors.
__device__ float g_gh[N_ * C_ * H_];   // [n][ch][h]  mean over w
__device__ float g_gw[N_ * C_ * W_];   // [n][ch][w]  mean over h
__device__ float g_ah[N_ * C_ * H_];   // sigmoid gate along h
__device__ float g_aw[N_ * C_ * W_];   // sigmoid gate along w

// ---------------------------------------------------------------------------
// Kernel 1: per-(n,ch) 64x64 tile -> row means (gh) and col means (gw).
// Processes x in INCREASING address order, leaving the tail of x in L2.
// ---------------------------------------------------------------------------
__global__ __launch_bounds__(256) void pool_kernel(const float* __restrict__ x) {
    __shared__ float xs[64 * 65];
    const int img = blockIdx.x;                 // n*512 + ch
    const float4* __restrict__ xp = (const float4*)(x + (size_t)img * 4096);
    const int tid = threadIdx.x;

#pragma unroll
    for (int k = 0; k < 4; k++) {
        int idx4 = k * 256 + tid;
        float4 v = xp[idx4];
        int f = idx4 << 2;
        int h = f >> 6, w = f & 63;
        float* p = &xs[h * 65 + w];
        p[0] = v.x; p[1] = v.y; p[2] = v.z; p[3] = v.w;
    }
    __syncthreads();

    if (tid < 64) {
        float s = 0.f;
#pragma unroll
        for (int i = 0; i < 64; i++) s += xs[tid * 65 + i];
        g_gh[img * 64 + tid] = s * (1.f / 64.f);
    } else if (tid < 128) {
        int w = tid - 64;
        float s = 0.f;
#pragma unroll
        for (int i = 0; i < 64; i++) s += xs[i * 65 + w];
        g_gw[img * 64 + w] = s * (1.f / 64.f);
    }
}

// ---------------------------------------------------------------------------
// Kernel 2: per-(n,g) tiny MLP + BN + hard-swish + two sigmoid gate GEMMs.
// 64 blocks x 128 threads. All weights cached in smem. ~4 MB footprint; barely
// perturbs the x data resident in L2.
// ---------------------------------------------------------------------------
__global__ __launch_bounds__(128) void mlp_kernel(
    const float* __restrict__ W1, const float* __restrict__ b1,
    const float* __restrict__ gamma, const float* __restrict__ beta,
    const float* __restrict__ mean_, const float* __restrict__ var_,
    const float* __restrict__ Wh, const float* __restrict__ bh,
    const float* __restrict__ Ww, const float* __restrict__ bw)
{
    __shared__ float W1s[MIP * CG];   // [m][c]
    __shared__ float ys[MIP * 128];   // [m][l]  post-activation
    __shared__ float Whs[CG * MIP];   // [c][m]
    __shared__ float Wws[CG * MIP];   // [c][m]
    __shared__ float bhs[CG], bws[CG];
    __shared__ float scale_s[MIP], shift_s[MIP], b1s[MIP];

    const int tid = threadIdx.x;          // 0..127
    const int blk = blockIdx.x;           // n*4 + g
    const int n = blk >> 2, g = blk & 3;

    for (int i = tid; i < MIP * CG; i += 128) {
        W1s[i] = W1[i];
        Whs[i] = Wh[i];
        Wws[i] = Ww[i];
    }
    bhs[tid] = bh[tid];
    bws[tid] = bw[tid];
    if (tid < MIP) {
        float sc = gamma[tid] * rsqrtf(var_[tid] + EPS_);
        scale_s[tid] = sc;
        shift_s[tid] = beta[tid] - mean_[tid] * sc;
        b1s[tid] = b1[tid];
    }
    __syncthreads();

    // ---- phase 1: y[m][l] = sum_c W1[m][c] * Y[c][l]; thread = l ----
    const int l = tid;
    const float* __restrict__ src = (l < 64)
        ? &g_gh[((size_t)n * C_ + g * CG) * 64 + l]
        : &g_gw[((size_t)n * C_ + g * CG) * 64 + (l - 64)];

    float acc[MIP];
#pragma unroll
    for (int m = 0; m < MIP; m++) acc[m] = 0.f;

#pragma unroll 4
    for (int c = 0; c < CG; c++) {
        float yc = src[c * 64];            // coalesced across the block
#pragma unroll
        for (int m = 0; m < MIP; m++) acc[m] += W1s[m * CG + c] * yc;
    }

#pragma unroll
    for (int m = 0; m < MIP; m++) {
        float v = acc[m] + b1s[m];
        v = v * scale_s[m] + shift_s[m];             // BN (inference)
        float r = fminf(fmaxf(v + 3.f, 0.f), 6.f);   // hard-swish
        ys[m * 128 + l] = v * r * (1.f / 6.f);
    }
    __syncthreads();

    // ---- phase 2: gates. thread = c; ys reads are warp-broadcast ----
    const int c = tid;
    float whr[MIP], wwr[MIP];
#pragma unroll
    for (int m = 0; m < MIP; m++) {
        whr[m] = Whs[c * MIP + m];
        wwr[m] = Wws[c * MIP + m];
    }
    const float bhc = bhs[c], bwc = bws[c];
    const int ch = g * CG + c;
    float* __restrict__ ah_out = &g_ah[((size_t)n * C_ + ch) * 64];
    float* __restrict__ aw_out = &g_aw[((size_t)n * C_ + ch) * 64];

#pragma unroll 2
    for (int l2 = 0; l2 < 64; l2++) {
        float sh = bhc, sw2 = bwc;
#pragma unroll
        for (int m = 0; m < MIP; m++) {
            sh  += whr[m] * ys[m * 128 + l2];
            sw2 += wwr[m] * ys[m * 128 + l2 + 64];
        }
        ah_out[l2] = 1.f / (1.f + __expf(-sh));
        aw_out[l2] = 1.f / (1.f + __expf(-sw2));
    }
}

// ---------------------------------------------------------------------------
// Kernel 3: out[n][fc][h][w] = x[n][ch][h][w] * a_h[n][ch][h] * a_w[n][ch][w]
// with the channel shuffle fc = (ch % 4)*128 + ch/4.
// REVERSE blockIdx order: the first CTAs scheduled read the tail of x, which
// pool_kernel just left resident in L2 (x=128MB vs L2=126MB) -> the second
// x read is served mostly from L2 instead of DRAM.
// ---------------------------------------------------------------------------
__global__ __launch_bounds__(256) void apply_kernel(const float* __restrict__ x,
                                                    float* __restrict__ out) {
    __shared__ float sa[64], sw[64];
    const int img = (N_ * C_ - 1) - blockIdx.x;   // reversed traversal
    const int n = img >> 9, ch = img & 511;
    const int tid = threadIdx.x;

    if (tid < 64)       sa[tid]      = g_ah[img * 64 + tid];
    else if (tid < 128) sw[tid - 64] = g_aw[img * 64 + (tid - 64)];
    __syncthreads();

    const int fc = (ch & 3) * 128 + (ch >> 2);
    const float4* __restrict__ xp = (const float4*)(x + (size_t)img * 4096);
    float4* __restrict__ op = (float4*)(out + ((size_t)n * 512 + fc) * 4096);

#pragma unroll
    for (int k = 0; k < 4; k++) {
        int idx4 = k * 256 + tid;
        float4 v = xp[idx4];
        int f = idx4 << 2;
        int h = f >> 6, w = f & 63;
        float a = sa[h];
        v.x *= a * sw[w];
        v.y *= a * sw[w + 1];
        v.z *= a * sw[w + 2];
        v.w *= a * sw[w + 3];
        op[idx4] = v;
    }
}

extern "C" void kernel_launch(void* const* d_in, const int* in_sizes, int n_in,
                              void* d_out, int out_size) {
    const float* x     = (const float*)d_in[0];
    const float* W1    = (const float*)d_in[1];
    const float* b1    = (const float*)d_in[2];
    const float* gamma = (const float*)d_in[3];
    const float* beta  = (const float*)d_in[4];
    const float* mean_ = (const float*)d_in[5];
    const float* var_  = (const float*)d_in[6];
    const float* Wh    = (const float*)d_in[7];
    const float* bh    = (const float*)d_in[8];
    const float* Ww    = (const float*)d_in[9];
    const float* bw    = (const float*)d_in[10];
    float* out = (float*)d_out;

    pool_kernel<<<N_ * C_, 256>>>(x);
    mlp_kernel<<<N_ * GRP, 128>>>(W1, b1, gamma, beta, mean_, var_, Wh, bh, Ww, bw);
    apply_kernel<<<N_ * C_, 256>>>(x, out);
}